// round 16
// baseline (speedup 1.0000x reference)
#include <cuda_runtime.h>
#include <cuda_fp16.h>
#include <cstdint>

#define N_USERS 50000
#define N_ITEMS 100000
#define N_NODES (N_USERS + N_ITEMS)
#define D 64
#define EPS 1e-6f
#define E_MAX 2400000
#define SCAN_BLOCK 1024
#define N_SCAN_BLOCKS ((N_NODES + SCAN_BLOCK - 1) / SCAN_BLOCK)   // 147
#define DEG_BUCKETS 64

// ---------------------------------------------------------------------------
// Static scratch (allocation-free). Device symbols are ONLY referenced from
// device code. fp16-only embedding storage (R11 win); arithmetic fp32.
// ---------------------------------------------------------------------------
__device__ __half2 g_embh[4][N_NODES * D / 2];  // fp16 embeddings (layers 0..3)
__device__ int   g_cnt[N_NODES];               // per-row edge counts
__device__ int   g_row_ptr[N_NODES + 1];       // CSR row pointers
__device__ int   g_pos[E_MAX];                 // per-edge within-row rank (from hist)
__device__ int   g_csr_edge[E_MAX * 2];        // interleaved {col, val-bits} pairs
__device__ int   g_perm[N_NODES];              // degree-sorted node order
__device__ int   g_deghist[DEG_BUCKETS];       // degree histogram
__device__ int   g_degcur[DEG_BUCKETS];        // per-bucket scatter cursors
__device__ int   g_is64;                       // index dtype flag
__device__ int   g_done;                       // scan->scatter fence counter
// decoupled-lookback scan state (reset every launch by prep_init_kernel)
__device__ volatile int g_flag[N_SCAN_BLOCKS];
__device__ volatile int g_aggv[N_SCAN_BLOCKS];
__device__ volatile int g_incv[N_SCAN_BLOCKS];

// ---------------------------------------------------------------------------
// Prep + init fused: zero cnt/flags/done/deg state, detect index dtype, and
// write emb0 = fp16(concat(user_emb, item_emb)).
// ---------------------------------------------------------------------------
__global__ void prep_init_kernel(const float* __restrict__ user_emb,
                                 const float* __restrict__ item_emb,
                                 const void* rows, int n) {
    int i = blockIdx.x * blockDim.x + threadIdx.x;

    if (i < N_NODES) g_cnt[i] = 0;
    if (i < N_SCAN_BLOCKS) { g_flag[i] = 0; g_aggv[i] = 0; g_incv[i] = 0; }
    if (i < DEG_BUCKETS) { g_deghist[i] = 0; g_degcur[i] = 0; }
    if (i == 0) g_done = 0;

    const int total4 = N_NODES * D / 4;
    if (i < total4) {
        const int usplit = N_USERS * D / 4;
        float4 v = (i < usplit) ? ((const float4*)user_emb)[i]
                                : ((const float4*)item_emb)[i - usplit];
        g_embh[0][i * 2]     = __floats2half2_rn(v.x, v.y);
        g_embh[0][i * 2 + 1] = __floats2half2_rn(v.z, v.w);
    }

    if (blockIdx.x == 0) {
        __shared__ int s_bad;
        if (threadIdx.x == 0) s_bad = 0;
        __syncthreads();
        int lim = (n < 64) ? n : 64;
        if ((int)threadIdx.x < lim) {
            long long v = ((const long long*)rows)[threadIdx.x];
            if (v < 0 || v >= (long long)N_NODES) atomicOr(&s_bad, 1);
        }
        __syncthreads();
        if (threadIdx.x == 0) g_is64 = s_bad ? 0 : 1;
    }
}

__device__ __forceinline__ int load_idx(const void* p, int e) {
    if (g_is64) return (int)((const long long*)p)[e];
    return ((const int*)p)[e];
}

// ---------------------------------------------------------------------------
// Histogram + rank stash (atomic return value = edge's within-row slot).
// ---------------------------------------------------------------------------
__global__ void hist_kernel(const void* __restrict__ rows, int n_edges) {
    int e = blockIdx.x * blockDim.x + threadIdx.x;
    if (e >= n_edges) return;
    int r = load_idx(rows, e);
    g_pos[e] = atomicAdd(&g_cnt[r], 1);
}

// ---------------------------------------------------------------------------
// Fused scan + scatter + degree-sort permutation. Phase 1: block scan +
// degree histogram (shared->global). Grid-wide fence (147 resident blocks).
// Phase 2: redundant per-block 64-entry degree scan, counting-sort scatter
// of node ids into g_perm, then atomic-free edge scatter into packed CSR.
// ---------------------------------------------------------------------------
__global__ void scan_scatter_kernel(const void* __restrict__ rows,
                                    const void* __restrict__ cols,
                                    const float* __restrict__ vals,
                                    int n_edges) {
    __shared__ int sh[SCAN_BLOCK];
    __shared__ int s_exc;
    __shared__ int s_dh[DEG_BUCKETS];
    int b = blockIdx.x;
    int i = b * SCAN_BLOCK + threadIdx.x;
    int v = (i < N_NODES) ? g_cnt[i] : 0;
    int dcl = (v < DEG_BUCKETS - 1) ? v : (DEG_BUCKETS - 1);

    if (threadIdx.x < DEG_BUCKETS) s_dh[threadIdx.x] = 0;
    sh[threadIdx.x] = v;
    __syncthreads();
    if (i < N_NODES) atomicAdd(&s_dh[dcl], 1);

    #pragma unroll
    for (int off = 1; off < SCAN_BLOCK; off <<= 1) {
        int t = (threadIdx.x >= off) ? sh[threadIdx.x - off] : 0;
        __syncthreads();
        sh[threadIdx.x] += t;
        __syncthreads();
    }
    int total = sh[SCAN_BLOCK - 1];

    // merge block degree histogram to global (before the grid fence)
    if (threadIdx.x < DEG_BUCKETS) atomicAdd(&g_deghist[threadIdx.x], s_dh[threadIdx.x]);

    if (threadIdx.x < 32) {                 // lookback warp
        int lane = threadIdx.x;
        if (b == 0) {
            if (lane == 0) {
                g_incv[0] = total;
                __threadfence();
                g_flag[0] = 2;
                s_exc = 0;
            }
        } else {
            if (lane == 0) {
                g_aggv[b] = total;
                __threadfence();
                g_flag[b] = 1;
            }
            int run = 0;
            int base = b;                    // window is [base-32, base)
            while (true) {
                int p = base - 32 + lane;
                int f, val;
                if (p >= 0) {
                    while ((f = g_flag[p]) == 0) { }
                    __threadfence();
                    val = (f == 2) ? g_incv[p] : g_aggv[p];
                } else {
                    f = 2; val = 0;
                }
                unsigned mask = __ballot_sync(0xFFFFFFFFu, f == 2);
                if (mask) {
                    int hi = 31 - __clz(mask);
                    int contrib = (lane >= hi) ? val : 0;
                    #pragma unroll
                    for (int o = 16; o; o >>= 1)
                        contrib += __shfl_xor_sync(0xFFFFFFFFu, contrib, o);
                    run += contrib;
                    break;
                } else {
                    int contrib = val;
                    #pragma unroll
                    for (int o = 16; o; o >>= 1)
                        contrib += __shfl_xor_sync(0xFFFFFFFFu, contrib, o);
                    run += contrib;
                    base -= 32;
                }
            }
            if (lane == 0) {
                g_incv[b] = run + total;
                __threadfence();
                g_flag[b] = 2;
                s_exc = run;
            }
        }
    }
    __syncthreads();

    if (i < N_NODES) {
        int inc = sh[threadIdx.x] + s_exc;
        g_row_ptr[i] = inc - v;              // exclusive
        if (i == N_NODES - 1) g_row_ptr[N_NODES] = inc;
    }
    __threadfence();
    __syncthreads();

    // grid-wide fence: row_ptr + deghist complete before perm/scatter
    if (threadIdx.x == 0) {
        atomicAdd(&g_done, 1);
        while (atomicAdd(&g_done, 0) < (int)gridDim.x) { }
    }
    __syncthreads();

    // redundant per-block exclusive scan of the 64-entry degree histogram
    __shared__ int s_doff[DEG_BUCKETS];
    if (threadIdx.x == 0) {
        int run = 0;
        for (int k = 0; k < DEG_BUCKETS; k++) {
            int t = g_deghist[k];
            s_doff[k] = run;
            run += t;
        }
    }
    __syncthreads();

    // counting-sort scatter: node ids into degree-sorted g_perm
    if (i < N_NODES) {
        int posn = atomicAdd(&g_degcur[dcl], 1);
        g_perm[s_doff[dcl] + posn] = i;
    }

    // Phase 2: scatter this block's edge slice (atomic-free, packed 8B store)
    int per = (n_edges + gridDim.x - 1) / gridDim.x;
    int s0 = b * per;
    int s1 = s0 + per; if (s1 > n_edges) s1 = n_edges;
    for (int e = s0 + threadIdx.x; e < s1; e += SCAN_BLOCK) {
        int r = load_idx(rows, e);
        int c = load_idx(cols, e);
        float vv = vals[e];
        int slot = __ldcg(&g_row_ptr[r]) + g_pos[e];
        ((int2*)g_csr_edge)[slot] = make_int2(c, __float_as_int(vv));
    }
}

// ---------------------------------------------------------------------------
// Fused layer — 4 nodes/warp, 8 lanes/node, 8 dims/lane (R14-proven loop),
// nodes taken in DEGREE-SORTED order via g_perm so the 4 nodes in a warp
// have near-equal trip counts (kills ~25% max-of-4 divergence waste).
// fp32 math, fp16 storage. Arithmetic per node is bit-identical to R14.
// ---------------------------------------------------------------------------
__global__ void layer_kernel(int l) {
    int warp = blockIdx.x * (blockDim.x >> 5) + (threadIdx.x >> 5);
    int lane = threadIdx.x & 31;
    int grp  = lane >> 3;          // node-slot within warp (0..3)
    int sub  = lane & 7;           // 16B slice within 128B row
    int idx  = warp * 4 + grp;
    if (idx >= N_NODES) return;    // whole warp exits together (N_NODES%4==0)
    int node = __ldg(&g_perm[idx]);

    const char* baseb = (const char*)g_embh[l];
    char*       outb  = (char*)g_embh[l + 1];
    int slice = sub * 16;

    int beg = __ldg(&g_row_ptr[node]);
    int end = __ldg(&g_row_ptr[node + 1]);

    float acc[8];
    #pragma unroll
    for (int k = 0; k < 8; k++) acc[k] = 0.f;

    for (int i = beg; i < end; i++) {
        int2 e = __ldg(&((const int2*)g_csr_edge)[i]);
        float v = __int_as_float(e.y);
        uint4 raw = __ldg((const uint4*)(baseb + (size_t)e.x * 128 + slice));
        float2 f0 = __half22float2(*(__half2*)&raw.x);
        float2 f1 = __half22float2(*(__half2*)&raw.y);
        float2 f2 = __half22float2(*(__half2*)&raw.z);
        float2 f3 = __half22float2(*(__half2*)&raw.w);
        acc[0] += v * f0.x;  acc[1] += v * f0.y;
        acc[2] += v * f1.x;  acc[3] += v * f1.y;
        acc[4] += v * f2.x;  acc[5] += v * f2.y;
        acc[6] += v * f3.x;  acc[7] += v * f3.y;
    }

    // self row slice
    uint4 so = __ldg((const uint4*)(baseb + (size_t)node * 128 + slice));
    float o[8];
    {
        float2 f0 = __half22float2(*(__half2*)&so.x);
        float2 f1 = __half22float2(*(__half2*)&so.y);
        float2 f2 = __half22float2(*(__half2*)&so.z);
        float2 f3 = __half22float2(*(__half2*)&so.w);
        o[0] = f0.x; o[1] = f0.y; o[2] = f1.x; o[3] = f1.y;
        o[4] = f2.x; o[5] = f2.y; o[6] = f3.x; o[7] = f3.y;
    }

    float s = 0.f;
    #pragma unroll
    for (int k = 0; k < 8; k++) {
        float d = o[k] - acc[k] + EPS;
        s += d * d;
    }
    __syncwarp();
    // reduce over the 8 lanes of this node (xor offsets stay in-group)
    s += __shfl_xor_sync(0xFFFFFFFFu, s, 1);
    s += __shfl_xor_sync(0xFFFFFFFFu, s, 2);
    s += __shfl_xor_sync(0xFFFFFFFFu, s, 4);

    float osn   = sqrtf(s);
    float dnew  = log1pf(osn);
    float inv   = 1.0f / (1.0f + dnew);
    float w_old = inv;
    float w_new = dnew * inv;

    uint4 outv;
    ((__half2*)&outv.x)[0] = __floats2half2_rn(w_old * o[0] + w_new * acc[0],
                                               w_old * o[1] + w_new * acc[1]);
    ((__half2*)&outv.y)[0] = __floats2half2_rn(w_old * o[2] + w_new * acc[2],
                                               w_old * o[3] + w_new * acc[3]);
    ((__half2*)&outv.z)[0] = __floats2half2_rn(w_old * o[4] + w_new * acc[4],
                                               w_old * o[5] + w_new * acc[5]);
    ((__half2*)&outv.w)[0] = __floats2half2_rn(w_old * o[6] + w_new * acc[6],
                                               w_old * o[7] + w_new * acc[7]);
    *(uint4*)(outb + (size_t)node * 128 + slice) = outv;
}

// ---------------------------------------------------------------------------
// Gather: out row = fp32 mean over the 4 fp16 layer embeddings.
// ---------------------------------------------------------------------------
__global__ void gather_kernel(const void* __restrict__ user_id,
                              const void* __restrict__ item_id,
                              float* __restrict__ out,
                              int n_ids) {
    int i = blockIdx.x * (blockDim.x >> 5) + (threadIdx.x >> 5);
    int lane = threadIdx.x & 31;
    if (i >= 2 * n_ids) return;

    int node;
    if (i < n_ids) node = load_idx(user_id, i);
    else           node = N_USERS + load_idx(item_id, i - n_ids);

    int off = node * 32 + lane;
    float2 a0 = __half22float2(g_embh[0][off]);
    float2 a1 = __half22float2(g_embh[1][off]);
    float2 a2 = __half22float2(g_embh[2][off]);
    float2 a3 = __half22float2(g_embh[3][off]);
    float2 r;
    r.x = (a0.x + a1.x + a2.x + a3.x) * 0.25f;
    r.y = (a0.y + a1.y + a2.y + a3.y) * 0.25f;
    ((float2*)(out + (long long)i * D))[lane] = r;
}

// ---------------------------------------------------------------------------
// kernel_launch — layer_kernel(0) stays at stream position 3 (profiled slot).
// ---------------------------------------------------------------------------
extern "C" void kernel_launch(void* const* d_in, const int* in_sizes, int n_in,
                              void* d_out, int out_size) {
    const float* user_emb = (const float*)d_in[0];
    const float* item_emb = (const float*)d_in[1];
    const float* adj_vals = (const float*)d_in[2];
    const void*  adj_rows = d_in[3];
    const void*  adj_cols = d_in[4];
    const void*  user_id  = d_in[5];
    const void*  item_id  = d_in[6];
    float* out = (float*)d_out;

    int n_edges = in_sizes[3];
    if (n_edges > E_MAX) n_edges = E_MAX;
    int n_ids = in_sizes[5];

    // 0: prep + init (zero state + dtype detect + emb0 fp16)
    {
        int total4 = N_NODES * D / 4;
        prep_init_kernel<<<(total4 + 255) / 256, 256>>>(user_emb, item_emb,
                                                        adj_rows, n_edges);
    }
    // 1: histogram + per-edge rank stash
    hist_kernel<<<(n_edges + 255) / 256, 256>>>(adj_rows, n_edges);
    // 2: fused scan + degree-sort perm + scatter
    scan_scatter_kernel<<<N_SCAN_BLOCKS, SCAN_BLOCK>>>(adj_rows, adj_cols,
                                                       adj_vals, n_edges);
    // 3-5: fused layers (4 degree-sorted nodes per warp, 8 warps per block)
    {
        int warps = (N_NODES + 3) / 4;
        int layer_blocks = (warps + 7) / 8;
        layer_kernel<<<layer_blocks, 256>>>(0);
        layer_kernel<<<layer_blocks, 256>>>(1);
        layer_kernel<<<layer_blocks, 256>>>(2);
    }
    // 6: final gather + mean
    int gather_rows = 2 * n_ids;
    gather_kernel<<<(gather_rows + 7) / 8, 256>>>(user_id, item_id, out, n_ids);
}

// round 17
// speedup vs baseline: 1.1409x; 1.1409x over previous
#include <cuda_runtime.h>
#include <cuda_fp16.h>
#include <cstdint>

#define N_USERS 50000
#define N_ITEMS 100000
#define N_NODES (N_USERS + N_ITEMS)
#define D 64
#define EPS 1e-6f
#define E_MAX 2400000
#define SCAN_BLOCK 1024
#define N_SCAN_BLOCKS ((N_NODES + SCAN_BLOCK - 1) / SCAN_BLOCK)   // 147
#define DEG_BUCKETS 64

// ---------------------------------------------------------------------------
// Static scratch (allocation-free). Device symbols are ONLY referenced from
// device code. fp16-only embedding storage (R11 win); arithmetic fp32.
// ---------------------------------------------------------------------------
__device__ __half2 g_embh[4][N_NODES * D / 2];  // fp16 embeddings (layers 0..3)
__device__ int   g_cnt[N_NODES];               // per-row edge counts
__device__ int   g_row_ptr[N_NODES + 1];       // CSR row pointers
__device__ int   g_pos[E_MAX];                 // per-edge within-row rank (from hist)
__device__ int   g_csr_edge[E_MAX * 2];        // interleaved {col, val-bits} pairs
__device__ int   g_perm[N_NODES];              // degree-sorted node order
__device__ int   g_deghist[DEG_BUCKETS];       // degree histogram (reservation base)
__device__ int   g_is64;                       // index dtype flag
__device__ int   g_done;                       // scan->scatter fence counter
// decoupled-lookback scan state (reset every launch by prep_init_kernel)
__device__ volatile int g_flag[N_SCAN_BLOCKS];
__device__ volatile int g_aggv[N_SCAN_BLOCKS];
__device__ volatile int g_incv[N_SCAN_BLOCKS];

// ---------------------------------------------------------------------------
// Prep + init fused: zero cnt/flags/done/deg state, detect index dtype, and
// write emb0 = fp16(concat(user_emb, item_emb)).
// ---------------------------------------------------------------------------
__global__ void prep_init_kernel(const float* __restrict__ user_emb,
                                 const float* __restrict__ item_emb,
                                 const void* rows, int n) {
    int i = blockIdx.x * blockDim.x + threadIdx.x;

    if (i < N_NODES) g_cnt[i] = 0;
    if (i < N_SCAN_BLOCKS) { g_flag[i] = 0; g_aggv[i] = 0; g_incv[i] = 0; }
    if (i < DEG_BUCKETS) g_deghist[i] = 0;
    if (i == 0) g_done = 0;

    const int total4 = N_NODES * D / 4;
    if (i < total4) {
        const int usplit = N_USERS * D / 4;
        float4 v = (i < usplit) ? ((const float4*)user_emb)[i]
                                : ((const float4*)item_emb)[i - usplit];
        g_embh[0][i * 2]     = __floats2half2_rn(v.x, v.y);
        g_embh[0][i * 2 + 1] = __floats2half2_rn(v.z, v.w);
    }

    if (blockIdx.x == 0) {
        __shared__ int s_bad;
        if (threadIdx.x == 0) s_bad = 0;
        __syncthreads();
        int lim = (n < 64) ? n : 64;
        if ((int)threadIdx.x < lim) {
            long long v = ((const long long*)rows)[threadIdx.x];
            if (v < 0 || v >= (long long)N_NODES) atomicOr(&s_bad, 1);
        }
        __syncthreads();
        if (threadIdx.x == 0) g_is64 = s_bad ? 0 : 1;
    }
}

__device__ __forceinline__ int load_idx(const void* p, int e) {
    if (g_is64) return (int)((const long long*)p)[e];
    return ((const int*)p)[e];
}

// ---------------------------------------------------------------------------
// Histogram + rank stash (atomic return value = edge's within-row slot).
// ---------------------------------------------------------------------------
__global__ void hist_kernel(const void* __restrict__ rows, int n_edges) {
    int e = blockIdx.x * blockDim.x + threadIdx.x;
    if (e >= n_edges) return;
    int r = load_idx(rows, e);
    g_pos[e] = atomicAdd(&g_cnt[r], 1);
}

// ---------------------------------------------------------------------------
// Fused scan + scatter + degree-sort permutation (contention-free rebuild):
//   - within-block rank = return of SHARED histogram atomicAdd
//   - per-block bucket base = return of ONE global atomicAdd per bucket
//     (64 atomics/block; no per-node global atomics at all)
//   - post-fence bucket offsets: parallel load of g_deghist into shared,
//     then a 64-entry scan in smem (no serial global round-trips)
// ---------------------------------------------------------------------------
__global__ void scan_scatter_kernel(const void* __restrict__ rows,
                                    const void* __restrict__ cols,
                                    const float* __restrict__ vals,
                                    int n_edges) {
    __shared__ int sh[SCAN_BLOCK];
    __shared__ int s_exc;
    __shared__ int s_dh[DEG_BUCKETS];
    __shared__ int s_blkbase[DEG_BUCKETS];
    __shared__ int s_doff[DEG_BUCKETS];
    int b = blockIdx.x;
    int i = b * SCAN_BLOCK + threadIdx.x;
    int v = (i < N_NODES) ? g_cnt[i] : 0;
    int dcl = (v < DEG_BUCKETS - 1) ? v : (DEG_BUCKETS - 1);

    if (threadIdx.x < DEG_BUCKETS) s_dh[threadIdx.x] = 0;
    sh[threadIdx.x] = v;
    __syncthreads();
    int myrank = 0;
    if (i < N_NODES) myrank = atomicAdd(&s_dh[dcl], 1);   // within-block rank

    #pragma unroll
    for (int off = 1; off < SCAN_BLOCK; off <<= 1) {
        int t = (threadIdx.x >= off) ? sh[threadIdx.x - off] : 0;
        __syncthreads();
        sh[threadIdx.x] += t;
        __syncthreads();
    }
    int total = sh[SCAN_BLOCK - 1];

    // reserve this block's range in each bucket (64 global atomics/block)
    if (threadIdx.x < DEG_BUCKETS)
        s_blkbase[threadIdx.x] = atomicAdd(&g_deghist[threadIdx.x], s_dh[threadIdx.x]);

    if (threadIdx.x < 32) {                 // lookback warp
        int lane = threadIdx.x;
        if (b == 0) {
            if (lane == 0) {
                g_incv[0] = total;
                __threadfence();
                g_flag[0] = 2;
                s_exc = 0;
            }
        } else {
            if (lane == 0) {
                g_aggv[b] = total;
                __threadfence();
                g_flag[b] = 1;
            }
            int run = 0;
            int base = b;                    // window is [base-32, base)
            while (true) {
                int p = base - 32 + lane;
                int f, val;
                if (p >= 0) {
                    while ((f = g_flag[p]) == 0) { }
                    __threadfence();
                    val = (f == 2) ? g_incv[p] : g_aggv[p];
                } else {
                    f = 2; val = 0;
                }
                unsigned mask = __ballot_sync(0xFFFFFFFFu, f == 2);
                if (mask) {
                    int hi = 31 - __clz(mask);
                    int contrib = (lane >= hi) ? val : 0;
                    #pragma unroll
                    for (int o = 16; o; o >>= 1)
                        contrib += __shfl_xor_sync(0xFFFFFFFFu, contrib, o);
                    run += contrib;
                    break;
                } else {
                    int contrib = val;
                    #pragma unroll
                    for (int o = 16; o; o >>= 1)
                        contrib += __shfl_xor_sync(0xFFFFFFFFu, contrib, o);
                    run += contrib;
                    base -= 32;
                }
            }
            if (lane == 0) {
                g_incv[b] = run + total;
                __threadfence();
                g_flag[b] = 2;
                s_exc = run;
            }
        }
    }
    __syncthreads();

    if (i < N_NODES) {
        int inc = sh[threadIdx.x] + s_exc;
        g_row_ptr[i] = inc - v;              // exclusive
        if (i == N_NODES - 1) g_row_ptr[N_NODES] = inc;
    }
    __threadfence();
    __syncthreads();

    // grid-wide fence: row_ptr + deghist reservations complete
    if (threadIdx.x == 0) {
        atomicAdd(&g_done, 1);
        while (atomicAdd(&g_done, 0) < (int)gridDim.x) { }
    }
    __syncthreads();

    // bucket offsets: PARALLEL load of final counts, then 64-entry smem scan
    if (threadIdx.x < DEG_BUCKETS) s_doff[threadIdx.x] = g_deghist[threadIdx.x];
    __syncthreads();
    if (threadIdx.x == 0) {
        int run = 0;
        #pragma unroll
        for (int k = 0; k < DEG_BUCKETS; k++) {
            int t = s_doff[k];
            s_doff[k] = run;
            run += t;
        }
    }
    __syncthreads();

    // counting-sort write: no global atomics
    if (i < N_NODES)
        g_perm[s_doff[dcl] + s_blkbase[dcl] + myrank] = i;

    // Phase 2: scatter this block's edge slice (atomic-free, packed 8B store)
    int per = (n_edges + gridDim.x - 1) / gridDim.x;
    int s0 = b * per;
    int s1 = s0 + per; if (s1 > n_edges) s1 = n_edges;
    for (int e = s0 + threadIdx.x; e < s1; e += SCAN_BLOCK) {
        int r = load_idx(rows, e);
        int c = load_idx(cols, e);
        float vv = vals[e];
        int slot = __ldcg(&g_row_ptr[r]) + g_pos[e];
        ((int2*)g_csr_edge)[slot] = make_int2(c, __float_as_int(vv));
    }
}

// ---------------------------------------------------------------------------
// Fused layer — 4 nodes/warp, 8 lanes/node, 8 dims/lane, degree-sorted node
// order via g_perm (R16-measured: 42.0us). fp32 math, fp16 storage.
// ---------------------------------------------------------------------------
__global__ void layer_kernel(int l) {
    int warp = blockIdx.x * (blockDim.x >> 5) + (threadIdx.x >> 5);
    int lane = threadIdx.x & 31;
    int grp  = lane >> 3;          // node-slot within warp (0..3)
    int sub  = lane & 7;           // 16B slice within 128B row
    int idx  = warp * 4 + grp;
    if (idx >= N_NODES) return;    // whole warp exits together (N_NODES%4==0)
    int node = __ldg(&g_perm[idx]);

    const char* baseb = (const char*)g_embh[l];
    char*       outb  = (char*)g_embh[l + 1];
    int slice = sub * 16;

    int beg = __ldg(&g_row_ptr[node]);
    int end = __ldg(&g_row_ptr[node + 1]);

    float acc[8];
    #pragma unroll
    for (int k = 0; k < 8; k++) acc[k] = 0.f;

    for (int i = beg; i < end; i++) {
        int2 e = __ldg(&((const int2*)g_csr_edge)[i]);
        float v = __int_as_float(e.y);
        uint4 raw = __ldg((const uint4*)(baseb + (size_t)e.x * 128 + slice));
        float2 f0 = __half22float2(*(__half2*)&raw.x);
        float2 f1 = __half22float2(*(__half2*)&raw.y);
        float2 f2 = __half22float2(*(__half2*)&raw.z);
        float2 f3 = __half22float2(*(__half2*)&raw.w);
        acc[0] += v * f0.x;  acc[1] += v * f0.y;
        acc[2] += v * f1.x;  acc[3] += v * f1.y;
        acc[4] += v * f2.x;  acc[5] += v * f2.y;
        acc[6] += v * f3.x;  acc[7] += v * f3.y;
    }

    // self row slice
    uint4 so = __ldg((const uint4*)(baseb + (size_t)node * 128 + slice));
    float o[8];
    {
        float2 f0 = __half22float2(*(__half2*)&so.x);
        float2 f1 = __half22float2(*(__half2*)&so.y);
        float2 f2 = __half22float2(*(__half2*)&so.z);
        float2 f3 = __half22float2(*(__half2*)&so.w);
        o[0] = f0.x; o[1] = f0.y; o[2] = f1.x; o[3] = f1.y;
        o[4] = f2.x; o[5] = f2.y; o[6] = f3.x; o[7] = f3.y;
    }

    float s = 0.f;
    #pragma unroll
    for (int k = 0; k < 8; k++) {
        float d = o[k] - acc[k] + EPS;
        s += d * d;
    }
    __syncwarp();
    // reduce over the 8 lanes of this node (xor offsets stay in-group)
    s += __shfl_xor_sync(0xFFFFFFFFu, s, 1);
    s += __shfl_xor_sync(0xFFFFFFFFu, s, 2);
    s += __shfl_xor_sync(0xFFFFFFFFu, s, 4);

    float osn   = sqrtf(s);
    float dnew  = log1pf(osn);
    float inv   = 1.0f / (1.0f + dnew);
    float w_old = inv;
    float w_new = dnew * inv;

    uint4 outv;
    ((__half2*)&outv.x)[0] = __floats2half2_rn(w_old * o[0] + w_new * acc[0],
                                               w_old * o[1] + w_new * acc[1]);
    ((__half2*)&outv.y)[0] = __floats2half2_rn(w_old * o[2] + w_new * acc[2],
                                               w_old * o[3] + w_new * acc[3]);
    ((__half2*)&outv.z)[0] = __floats2half2_rn(w_old * o[4] + w_new * acc[4],
                                               w_old * o[5] + w_new * acc[5]);
    ((__half2*)&outv.w)[0] = __floats2half2_rn(w_old * o[6] + w_new * acc[6],
                                               w_old * o[7] + w_new * acc[7]);
    *(uint4*)(outb + (size_t)node * 128 + slice) = outv;
}

// ---------------------------------------------------------------------------
// Gather: out row = fp32 mean over the 4 fp16 layer embeddings.
// ---------------------------------------------------------------------------
__global__ void gather_kernel(const void* __restrict__ user_id,
                              const void* __restrict__ item_id,
                              float* __restrict__ out,
                              int n_ids) {
    int i = blockIdx.x * (blockDim.x >> 5) + (threadIdx.x >> 5);
    int lane = threadIdx.x & 31;
    if (i >= 2 * n_ids) return;

    int node;
    if (i < n_ids) node = load_idx(user_id, i);
    else           node = N_USERS + load_idx(item_id, i - n_ids);

    int off = node * 32 + lane;
    float2 a0 = __half22float2(g_embh[0][off]);
    float2 a1 = __half22float2(g_embh[1][off]);
    float2 a2 = __half22float2(g_embh[2][off]);
    float2 a3 = __half22float2(g_embh[3][off]);
    float2 r;
    r.x = (a0.x + a1.x + a2.x + a3.x) * 0.25f;
    r.y = (a0.y + a1.y + a2.y + a3.y) * 0.25f;
    ((float2*)(out + (long long)i * D))[lane] = r;
}

// ---------------------------------------------------------------------------
// kernel_launch — layer_kernel(0) stays at stream position 3 (profiled slot).
// ---------------------------------------------------------------------------
extern "C" void kernel_launch(void* const* d_in, const int* in_sizes, int n_in,
                              void* d_out, int out_size) {
    const float* user_emb = (const float*)d_in[0];
    const float* item_emb = (const float*)d_in[1];
    const float* adj_vals = (const float*)d_in[2];
    const void*  adj_rows = d_in[3];
    const void*  adj_cols = d_in[4];
    const void*  user_id  = d_in[5];
    const void*  item_id  = d_in[6];
    float* out = (float*)d_out;

    int n_edges = in_sizes[3];
    if (n_edges > E_MAX) n_edges = E_MAX;
    int n_ids = in_sizes[5];

    // 0: prep + init (zero state + dtype detect + emb0 fp16)
    {
        int total4 = N_NODES * D / 4;
        prep_init_kernel<<<(total4 + 255) / 256, 256>>>(user_emb, item_emb,
                                                        adj_rows, n_edges);
    }
    // 1: histogram + per-edge rank stash
    hist_kernel<<<(n_edges + 255) / 256, 256>>>(adj_rows, n_edges);
    // 2: fused scan + degree-sort perm + scatter (contention-free perm build)
    scan_scatter_kernel<<<N_SCAN_BLOCKS, SCAN_BLOCK>>>(adj_rows, adj_cols,
                                                       adj_vals, n_edges);
    // 3-5: fused layers (4 degree-sorted nodes per warp, 8 warps per block)
    {
        int warps = (N_NODES + 3) / 4;
        int layer_blocks = (warps + 7) / 8;
        layer_kernel<<<layer_blocks, 256>>>(0);
        layer_kernel<<<layer_blocks, 256>>>(1);
        layer_kernel<<<layer_blocks, 256>>>(2);
    }
    // 6: final gather + mean
    int gather_rows = 2 * n_ids;
    gather_kernel<<<(gather_rows + 7) / 8, 256>>>(user_id, item_id, out, n_ids);
}